// round 9
// baseline (speedup 1.0000x reference)
#include <cuda_runtime.h>
#include <cstdint>

#define N_NODES 50000
#define N_EDGES 800000
#define DNODE   128
#define DEDGE   32
#define HID     128
#define NSM     148

typedef unsigned long long u64;

// ---------------- device-global scratch (no allocations allowed) ----------------
__device__ int   g_src[N_EDGES];
__device__ int   g_dst[N_EDGES];
__device__ float g_mi[(size_t)N_NODES * HID];      // 25.6 MB scatter target
__device__ float g_P[(size_t)N_NODES * 256];       // 51.2 MB: [h@W1a | h@W1b]
__device__ float g_W1r[288 * 128];                 // We1, tf32-rounded (RNA), [K][N]
__device__ float g_W2r[128 * 128];                 // We2, tf32-rounded (RNA), [K][N]
__device__ float g_Wh1hi[256 * 128];               // Wh1 split hi/lo (3xTF32)
__device__ float g_Wh1lo[256 * 128];
__device__ float g_Wh2hi[128 * 128];
__device__ float g_Wh2lo[128 * 128];

// ---------------- helpers ----------------
__device__ __forceinline__ uint32_t smem_u32(const void* p) {
    uint32_t a;
    asm("{ .reg .u64 t; cvta.to.shared.u64 t, %1; cvt.u32.u64 %0, t; }" : "=r"(a) : "l"(p));
    return a;
}
__device__ __forceinline__ uint32_t rna(float x) {
    uint32_t r; asm("cvt.rna.tf32.f32 %0, %1;" : "=r"(r) : "f"(x)); return r;
}

#define CP_ASYNC(ds, gp) \
    asm volatile("cp.async.cg.shared.global [%0], [%1], 16;" :: "r"(ds), "l"(gp))
#define CP_COMMIT() asm volatile("cp.async.commit_group;" ::: "memory")
#define CP_WAIT1()  asm volatile("cp.async.wait_group 1;" ::: "memory")
#define CP_WAIT0()  asm volatile("cp.async.wait_group 0;" ::: "memory")

#define MMA_TF32(C, a0, a1, a2, a3, b0, b1) \
    asm volatile("mma.sync.aligned.m16n8k8.row.col.f32.tf32.tf32.f32 " \
        "{%0,%1,%2,%3}, {%4,%5,%6,%7}, {%8,%9}, {%0,%1,%2,%3};" \
        : "+f"((C)[0]), "+f"((C)[1]), "+f"((C)[2]), "+f"((C)[3]) \
        : "r"(a0), "r"(a1), "r"(a2), "r"(a3), "r"(b0), "r"(b1))

// ---------------- aux kernel: dtype-detect + index convert + zero g_mi ----------------
__global__ void convert_kernel(const void* __restrict__ ei) {
    __shared__ int s64;
    if (threadIdx.x == 0) {
        const int* p = (const int*)ei;
        int all0 = 1;
        for (int s = 0; s < 256; s++)
            if (p[2 * s + 1] != 0) { all0 = 0; break; }
        s64 = all0;
    }
    __syncthreads();
    int i = blockIdx.x * blockDim.x + threadIdx.x;
    if (i < N_EDGES) {
        if (s64) {
            const long long* p = (const long long*)ei;
            g_src[i] = (int)p[i];
            g_dst[i] = (int)p[N_EDGES + i];
        } else {
            const int* p = (const int*)ei;
            g_src[i] = p[i];
            g_dst[i] = p[N_EDGES + i];
        }
    }
    size_t n4 = (size_t)N_NODES * HID / 4;
    float4 z = make_float4(0.f, 0.f, 0.f, 0.f);
    for (size_t j = (size_t)blockIdx.x * blockDim.x + threadIdx.x; j < n4;
         j += (size_t)gridDim.x * blockDim.x)
        ((float4*)g_mi)[j] = z;
}

// ---------------- prep: RNA-round edge weights, split node weights hi/lo ----------------
__global__ void prep_kernel(const float* __restrict__ W1, const float* __restrict__ W2,
                            const float* __restrict__ Wh1, const float* __restrict__ Wh2) {
    int t = blockIdx.x * blockDim.x + threadIdx.x;
    int stride = gridDim.x * blockDim.x;
    for (int i = t; i < 288 * 128; i += stride)
        g_W1r[i] = __uint_as_float(rna(W1[i]));
    for (int i = t; i < 128 * 128; i += stride)
        g_W2r[i] = __uint_as_float(rna(W2[i]));
    for (int i = t; i < 256 * 128; i += stride) {
        float w = Wh1[i];
        uint32_t hi = rna(w);
        g_Wh1hi[i] = __uint_as_float(hi);
        g_Wh1lo[i] = __uint_as_float(rna(w - __uint_as_float(hi)));
    }
    for (int i = t; i < 128 * 128; i += stride) {
        float w = Wh2[i];
        uint32_t hi = rna(w);
        g_Wh2hi[i] = __uint_as_float(hi);
        g_Wh2lo[i] = __uint_as_float(rna(w - __uint_as_float(hi)));
    }
}

// =================================================================
// Precompute P = h @ [We1_a | We1_b]  (50k x 128 x 256, tf32 mma)
// =================================================================
#define GP_SMEM 98304

__global__ __launch_bounds__(256) void gemm_P(const float* __restrict__ h) {
    extern __shared__ char sm[];
    const uint32_t smb = smem_u32(sm);
    const int tid = threadIdx.x, lane = tid & 31, wid = tid >> 5;
    const int g = lane >> 2, t4 = lane & 3;
    const int m0 = (wid >> 2) * 64, n0 = (wid & 3) * 64;
    const int r0 = blockIdx.x * 128;

    auto issue_x = [&](int ch, int b) {
        uint32_t xb = smb + b * 16384;
#pragma unroll
        for (int i = 0; i < 4; i++) {
            int f = tid + i * 256;
            int row = f >> 3, q = f & 7;
            int gr = r0 + row; if (gr >= N_NODES) gr = 0;
            const float* gp = h + (size_t)gr * DNODE + ch * 32 + q * 4;
            uint32_t ds = xb + 4u * (uint32_t)(row * 32 + ((4 * q) ^ (4 * (row & 7))));
            CP_ASYNC(ds, gp);
        }
    };
    auto issue_w = [&](int ch, int b) {
        uint32_t wb = smb + 32768 + b * 32768;
#pragma unroll
        for (int i = 0; i < 8; i++) {
            int f = tid + i * 256;
            int k = f >> 6, n4 = f & 63;
            int n = 4 * n4;
            const float* gp = (n < 128)
                ? g_W1r + (size_t)(ch * 32 + k) * 128 + n
                : g_W1r + (size_t)(128 + ch * 32 + k) * 128 + (n - 128);
            uint32_t ds = wb + 4u * (uint32_t)(k * 256 + (n ^ (8 * (k & 3))));
            CP_ASYNC(ds, gp);
        }
    };

    float c[4][8][4];
#pragma unroll
    for (int mf = 0; mf < 4; mf++)
#pragma unroll
        for (int nf = 0; nf < 8; nf++)
#pragma unroll
            for (int j = 0; j < 4; j++) c[mf][nf][j] = 0.0f;

    issue_x(0, 0); issue_w(0, 0); CP_COMMIT();
    for (int ch = 0; ch < 4; ch++) {
        if (ch < 3) {
            issue_x(ch + 1, (ch + 1) & 1);
            issue_w(ch + 1, (ch + 1) & 1);
            CP_COMMIT(); CP_WAIT1();
        } else CP_WAIT0();
        __syncthreads();
        const uint32_t* Xw = (const uint32_t*)sm + (ch & 1) * 4096;
        const uint32_t* Ww = (const uint32_t*)(sm + 32768) + (ch & 1) * 8192;
#pragma unroll
        for (int s = 0; s < 4; s++) {
            const int kb = 8 * s + t4;
            uint32_t b0r[8], b1r[8];
#pragma unroll
            for (int nf = 0; nf < 8; nf++) {
                int wc = (n0 + 8 * nf + g) ^ (8 * t4);
                b0r[nf] = Ww[kb * 256 + wc];
                b1r[nf] = Ww[(kb + 4) * 256 + wc];
            }
#pragma unroll
            for (int mf = 0; mf < 4; mf++) {
                int base = (m0 + mf * 16 + g) * 32;
                uint32_t a0 = Xw[base + (kb ^ (4 * g))];
                uint32_t a1 = Xw[base + 8 * 32 + (kb ^ (4 * g))];
                uint32_t a2 = Xw[base + ((kb + 4) ^ (4 * g))];
                uint32_t a3 = Xw[base + 8 * 32 + ((kb + 4) ^ (4 * g))];
#pragma unroll
                for (int nf = 0; nf < 8; nf++)
                    MMA_TF32(c[mf][nf], a0, a1, a2, a3, b0r[nf], b1r[nf]);
            }
        }
        __syncthreads();
    }

#pragma unroll
    for (int mf = 0; mf < 4; mf++) {
        int r = m0 + mf * 16 + g;
#pragma unroll
        for (int nf = 0; nf < 8; nf++) {
            int col = n0 + 8 * nf + 2 * t4;
            if (r0 + r < N_NODES)
                *(float2*)(g_P + (size_t)(r0 + r) * 256 + col) =
                    make_float2(c[mf][nf][0], c[mf][nf][1]);
            if (r0 + r + 8 < N_NODES)
                *(float2*)(g_P + (size_t)(r0 + r + 8) * 256 + col) =
                    make_float2(c[mf][nf][2], c[mf][nf][3]);
        }
    }
}

// =================================================================
// Edge kernel v5: PERSISTENT blocks (grid=148, 1 CTA/SM).
// W1e + W2 loaded to smem ONCE per SM; ea/src/dst double-buffered
// across tiles; phase 2 barrier-free inside.
// smem map (bytes), total 183296:
//   [0, 65536)        Ys: 128 rows x 128 words
//   [65536, 81920)    W1e (32k x 128n, swizzled)
//   [81920, 147456)   W2  (128k x 128n, swizzled)
//   [147456, 180224)  Xe[2]: ea tiles (16 KB each)
//   sb1@180224  sb2@180736  sSrc[2][128]@181248  sDst[2][128]@182272
// =================================================================
#define EDGE_SMEM 183296

__global__ __launch_bounds__(256, 1) void edge_kernel_p(
    const float* __restrict__ ea,
    const float* __restrict__ b1g, const float* __restrict__ b2g)
{
    extern __shared__ char sm[];
    const uint32_t smb = smem_u32(sm);
    float* Ys  = (float*)sm;
    float* sb1 = (float*)(sm + 180224);
    float* sb2 = (float*)(sm + 180736);
    int*   sSrc = (int*)(sm + 181248);   // [2][128]
    int*   sDst = (int*)(sm + 182272);   // [2][128]

    const int tid  = threadIdx.x;
    const int lane = tid & 31, wid = tid >> 5;
    const int g    = lane >> 2, t4 = lane & 3;
    const int m0   = (wid >> 1) * 32;
    const int n0   = (wid & 1) * 64;

    // ---- prime: biases, W1e, W2, tile-0 ea + indices ----
    if (tid < 128) { sb1[tid] = b1g[tid]; sb2[tid] = b2g[tid]; }
#pragma unroll
    for (int i = 0; i < 4; i++) {          // W1e: We1 rows 256..287
        int f = tid + i * 256;
        int k = f >> 5, n4 = f & 31;
        const float* gp = g_W1r + (size_t)(256 + k) * 128 + n4 * 4;
        uint32_t ds = smb + 65536 + 4u * (uint32_t)(k * 128 + ((4 * n4) ^ (8 * (k & 3))));
        CP_ASYNC(ds, gp);
    }
#pragma unroll
    for (int i = 0; i < 16; i++) {         // W2: all 128 k-rows
        int f = tid + i * 256;
        int k = f >> 5, n4 = f & 31;
        const float* gp = g_W2r + (size_t)k * 128 + n4 * 4;
        uint32_t ds = smb + 81920 + 4u * (uint32_t)(k * 128 + ((4 * n4) ^ (8 * (k & 3))));
        CP_ASYNC(ds, gp);
    }
    {
        int e0 = blockIdx.x * 128;
#pragma unroll
        for (int i = 0; i < 4; i++) {
            int f = tid + i * 256;
            int row = f >> 3, q = f & 7;
            const float* gp = ea + (size_t)(e0 + row) * DEDGE + q * 4;
            uint32_t ds = smb + 147456 +
                          4u * (uint32_t)(row * 32 + ((4 * q) ^ (4 * (row & 7))));
            CP_ASYNC(ds, gp);
        }
        if (tid < 128) {
            sSrc[tid] = g_src[e0 + tid];
            sDst[tid] = g_dst[e0 + tid];
        }
    }
    CP_COMMIT();
    CP_WAIT0();
    __syncthreads();

    auto compute = [&](const uint32_t* Xw, int rstride, int cofs,
                       const uint32_t* Ww, float (*c)[8][4]) {
#pragma unroll
        for (int s = 0; s < 4; s++) {
            const int kb = 8 * s + t4;
            uint32_t b0r[8], b1r[8];
#pragma unroll
            for (int nf = 0; nf < 8; nf++) {
                int wc = (n0 + 8 * nf + g) ^ (8 * t4);
                b0r[nf] = Ww[kb * 128 + wc];
                b1r[nf] = Ww[(kb + 4) * 128 + wc];
            }
#pragma unroll
            for (int mf = 0; mf < 2; mf++) {
                int base = (m0 + mf * 16 + g) * rstride + cofs;
                uint32_t a0 = Xw[base + (kb ^ (4 * g))];
                uint32_t a1 = Xw[base + 8 * rstride + (kb ^ (4 * g))];
                uint32_t a2 = Xw[base + ((kb + 4) ^ (4 * g))];
                uint32_t a3 = Xw[base + 8 * rstride + ((kb + 4) ^ (4 * g))];
#pragma unroll
                for (int nf = 0; nf < 8; nf++)
                    MMA_TF32(c[mf][nf], a0, a1, a2, a3, b0r[nf], b1r[nf]);
            }
        }
    };

    int b = 0;
    for (int t = blockIdx.x; t < N_EDGES / 128; t += NSM) {
        float c[2][8][4];
#pragma unroll
        for (int mf = 0; mf < 2; mf++)
#pragma unroll
            for (int nf = 0; nf < 8; nf++)
#pragma unroll
                for (int j = 0; j < 4; j++) c[mf][nf][j] = 0.0f;

        // ---- phase 1: T = ea @ We1_e  (Xe[b], W1e resident) ----
        compute((const uint32_t*)(sm + 147456) + b * 4096, 32, 0,
                (const uint32_t*)(sm + 65536), c);

        // ---- prefetch next tile (ea + indices) into parity b^1 ----
        const int tn = t + NSM;
        if (tn < N_EDGES / 128) {
            int e1 = tn * 128;
#pragma unroll
            for (int i = 0; i < 4; i++) {
                int f = tid + i * 256;
                int row = f >> 3, q = f & 7;
                const float* gp = ea + (size_t)(e1 + row) * DEDGE + q * 4;
                uint32_t ds = smb + 147456 + (b ^ 1) * 16384 +
                              4u * (uint32_t)(row * 32 + ((4 * q) ^ (4 * (row & 7))));
                CP_ASYNC(ds, gp);
            }
            CP_COMMIT();
            if (tid < 128) {
                sSrc[(b ^ 1) * 128 + tid] = g_src[e1 + tid];
                sDst[(b ^ 1) * 128 + tid] = g_dst[e1 + tid];
            }
        }

        // ---- epilogue A: raw T -> Ys (prev tile's scatter synced at loop bottom) ----
#pragma unroll
        for (int mf = 0; mf < 2; mf++) {
            int r0r = m0 + mf * 16 + g;
#pragma unroll
            for (int nf = 0; nf < 8; nf++) {
                int cc = n0 + 8 * nf + 2 * t4;
                int w = (cc & ~31) + ((cc & 31) ^ (4 * g));
                *(float2*)&Ys[r0r * 128 + w]       = make_float2(c[mf][nf][0], c[mf][nf][1]);
                *(float2*)&Ys[(r0r + 8) * 128 + w] = make_float2(c[mf][nf][2], c[mf][nf][3]);
#pragma unroll
                for (int j = 0; j < 4; j++) c[mf][nf][j] = 0.0f;
            }
        }
        __syncthreads();

        // ---- P-merge: Y = relu(T + P[src].lo + P[dst].hi + b1) ----
        const int* curS = sSrc + b * 128;
        const int* curD = sDst + b * 128;
#pragma unroll 4
        for (int i = 0; i < 16; i++) {
            int f = tid + i * 256;
            int row = f >> 5, c4 = f & 31;
            int w = row * 128 + (c4 >> 3) * 32 + ((4 * (c4 & 7)) ^ (4 * (row & 7)));
            float4 tt = *(const float4*)&Ys[w];
            float4 ps = *(const float4*)(g_P + (size_t)curS[row] * 256 + 4 * c4);
            float4 pd = *(const float4*)(g_P + (size_t)curD[row] * 256 + 128 + 4 * c4);
            float4 bb = *(const float4*)&sb1[4 * c4];
            float4 y;
            y.x = fmaxf(tt.x + ps.x + pd.x + bb.x, 0.0f);
            y.y = fmaxf(tt.y + ps.y + pd.y + bb.y, 0.0f);
            y.z = fmaxf(tt.z + ps.z + pd.z + bb.z, 0.0f);
            y.w = fmaxf(tt.w + ps.w + pd.w + bb.w, 0.0f);
            *(float4*)&Ys[w] = y;
        }
        __syncthreads();

        // ---- phase 2: layer 2, K=128, W2 resident, no internal syncs ----
#pragma unroll
        for (int ch = 0; ch < 4; ch++)
            compute((const uint32_t*)sm, 128, ch * 32,
                    (const uint32_t*)(sm + 81920) + ch * 32 * 128, c);
        __syncthreads();

        // ---- stage messages (+b2) into Ys ----
#pragma unroll
        for (int mf = 0; mf < 2; mf++) {
            int r0r = m0 + mf * 16 + g;
#pragma unroll
            for (int nf = 0; nf < 8; nf++) {
                int cc = n0 + 8 * nf + 2 * t4;
                float bb0 = sb2[cc], bb1 = sb2[cc + 1];
                int w = (cc & ~31) + ((cc & 31) ^ (4 * g));
                *(float2*)&Ys[r0r * 128 + w] =
                    make_float2(c[mf][nf][0] + bb0, c[mf][nf][1] + bb1);
                *(float2*)&Ys[(r0r + 8) * 128 + w] =
                    make_float2(c[mf][nf][2] + bb0, c[mf][nf][3] + bb1);
            }
        }
        __syncthreads();

        // ---- coalesced scatter-add ----
#pragma unroll 4
        for (int i = 0; i < 16; i++) {
            int f = tid + i * 256;
            int row = f >> 5, c4 = f & 31;
            int w = row * 128 + (c4 >> 3) * 32 + ((4 * (c4 & 7)) ^ (4 * (row & 7)));
            float4 v = *(const float4*)&Ys[w];
            float* gp = g_mi + (size_t)curD[row] * HID + 4 * c4;
            asm volatile("red.global.add.v4.f32 [%0], {%1,%2,%3,%4};"
                         :: "l"(gp), "f"(v.x), "f"(v.y), "f"(v.z), "f"(v.w) : "memory");
        }

        // ---- advance: wait next-tile ea, fence all (protects Ys + Xe reuse) ----
        b ^= 1;
        if (tn < N_EDGES / 128) CP_WAIT0();
        __syncthreads();
    }
}

// =================================================================
// Node MLP via 3xTF32 split mma (unchanged from R6)
// =================================================================
#define NODE_SMEM 99328

__global__ __launch_bounds__(256, 2) void node_kernel_m(
    const float* __restrict__ h,
    const float* __restrict__ b1g, const float* __restrict__ b2g,
    float* __restrict__ out)
{
    extern __shared__ char sm[];
    const uint32_t smb = smem_u32(sm);
    float* Ys  = (float*)sm;
    float* sb1 = (float*)(sm + 98304);
    float* sb2 = (float*)(sm + 98816);

    const int tid  = threadIdx.x;
    const int lane = tid & 31, wid = tid >> 5;
    const int g    = lane >> 2, t4 = lane & 3;
    const int m0   = (wid >> 1) * 16;
    const int n0   = (wid & 1) * 64;
    const int r0   = blockIdx.x * 64;

    if (tid < 128) { sb1[tid] = b1g[tid]; sb2[tid] = b2g[tid]; }

    auto issue_x = [&](int ch, int b) {
        uint32_t xb = smb + b * 8192;
#pragma unroll
        for (int i = 0; i < 2; i++) {
            int f = tid + i * 256;
            int row = f >> 3, q = f & 7;
            int gr = r0 + row; if (gr >= N_NODES) gr = 0;
            const float* gp = (ch < 4)
                ? h    + (size_t)gr * DNODE + ch * 32 + q * 4
                : g_mi + (size_t)gr * HID   + (ch - 4) * 32 + q * 4;
            uint32_t ds = xb + 4u * (uint32_t)(row * 32 + ((4 * q) ^ (4 * (row & 7))));
            CP_ASYNC(ds, gp);
        }
    };
    auto issue_w = [&](const float* Whi, const float* Wlo, int ch, int b) {
        uint32_t base_hi = smb + 32768 + b * 32768;
#pragma unroll
        for (int i = 0; i < 4; i++) {
            int f = tid + i * 256;
            int k = f >> 5, n4 = f & 31;
            uint32_t off = 4u * (uint32_t)(k * 128 + ((4 * n4) ^ (8 * (k & 3))));
            CP_ASYNC(base_hi + off,         Whi + (size_t)(ch * 32 + k) * 128 + n4 * 4);
            CP_ASYNC(base_hi + 16384 + off, Wlo + (size_t)(ch * 32 + k) * 128 + n4 * 4);
        }
    };

    float c[8][4];
#pragma unroll
    for (int nf = 0; nf < 8; nf++)
#pragma unroll
        for (int j = 0; j < 4; j++) c[nf][j] = 0.0f;

    auto computeN = [&](const uint32_t* Xw, int rstride, int cofs,
                        const uint32_t* Whi, const uint32_t* Wlo) {
#pragma unroll
        for (int s = 0; s < 4; s++) {
            const int kb = 8 * s + t4;
            int base0 = (m0 + g) * rstride + cofs;
            int base1 = (m0 + 8 + g) * rstride + cofs;
            float x0 = __uint_as_float(Xw[base0 + (kb ^ (4 * g))]);
            float x1 = __uint_as_float(Xw[base1 + (kb ^ (4 * g))]);
            float x2 = __uint_as_float(Xw[base0 + ((kb + 4) ^ (4 * g))]);
            float x3 = __uint_as_float(Xw[base1 + ((kb + 4) ^ (4 * g))]);
            uint32_t h0 = rna(x0), h1 = rna(x1), h2 = rna(x2), h3 = rna(x3);
            uint32_t l0 = rna(x0 - __uint_as_float(h0));
            uint32_t l1 = rna(x1 - __uint_as_float(h1));
            uint32_t l2 = rna(x2 - __uint_as_float(h2));
            uint32_t l3 = rna(x3 - __uint_as_float(h3));
#pragma unroll
            for (int nf = 0; nf < 8; nf++) {
                int wc = (n0 + 8 * nf + g) ^ (8 * t4);
                uint32_t bh0 = Whi[kb * 128 + wc], bh1 = Whi[(kb + 4) * 128 + wc];
                uint32_t bl0 = Wlo[kb * 128 + wc], bl1 = Wlo[(kb + 4) * 128 + wc];
                MMA_TF32(c[nf], h0, h1, h2, h3, bh0, bh1);
                MMA_TF32(c[nf], l0, l1, l2, l3, bh0, bh1);
                MMA_TF32(c[nf], h0, h1, h2, h3, bl0, bl1);
            }
        }
    };

    issue_x(0, 0); issue_w(g_Wh1hi, g_Wh1lo, 0, 0); CP_COMMIT();
    for (int ch = 0; ch < 8; ch++) {
        if (ch < 7) {
            issue_x(ch + 1, (ch + 1) & 1);
            issue_w(g_Wh1hi, g_Wh1lo, ch + 1, (ch + 1) & 1);
            CP_COMMIT(); CP_WAIT1();
        } else CP_WAIT0();
        __syncthreads();
        computeN((const uint32_t*)sm + (ch & 1) * 2048, 32, 0,
                 (const uint32_t*)(sm + 32768 + (ch & 1) * 32768),
                 (const uint32_t*)(sm + 32768 + (ch & 1) * 32768 + 16384));
        __syncthreads();
    }

#pragma unroll
    for (int nf = 0; nf < 8; nf++) {
        int cc = n0 + 8 * nf + 2 * t4;
        float bb0 = sb1[cc], bb1 = sb1[cc + 1];
        int w = (cc & ~31) + ((cc & 31) ^ (4 * g));
        *(float2*)&Ys[(m0 + g) * 128 + w] =
            make_float2(fmaxf(c[nf][0] + bb0, 0.0f), fmaxf(c[nf][1] + bb1, 0.0f));
        *(float2*)&Ys[(m0 + 8 + g) * 128 + w] =
            make_float2(fmaxf(c[nf][2] + bb0, 0.0f), fmaxf(c[nf][3] + bb1, 0.0f));
#pragma unroll
        for (int j = 0; j < 4; j++) c[nf][j] = 0.0f;
    }
    issue_w(g_Wh2hi, g_Wh2lo, 0, 0); CP_COMMIT();
    __syncthreads();

    for (int ch = 0; ch < 4; ch++) {
        if (ch < 3) {
            issue_w(g_Wh2hi, g_Wh2lo, ch + 1, (ch + 1) & 1);
            CP_COMMIT(); CP_WAIT1();
        } else CP_WAIT0();
        __syncthreads();
        computeN((const uint32_t*)sm, 128, ch * 32,
                 (const uint32_t*)(sm + 32768 + (ch & 1) * 32768),
                 (const uint32_t*)(sm + 32768 + (ch & 1) * 32768 + 16384));
        __syncthreads();
    }

#pragma unroll
    for (int nf = 0; nf < 8; nf++) {
        int cc = n0 + 8 * nf + 2 * t4;
        float bb0 = sb2[cc], bb1 = sb2[cc + 1];
        int ra = r0 + m0 + g, rb = ra + 8;
        if (ra < N_NODES)
            *(float2*)(out + (size_t)ra * 128 + cc) =
                make_float2(c[nf][0] + bb0, c[nf][1] + bb1);
        if (rb < N_NODES)
            *(float2*)(out + (size_t)rb * 128 + cc) =
                make_float2(c[nf][2] + bb0, c[nf][3] + bb1);
    }
}

// =================================================================
extern "C" void kernel_launch(void* const* d_in, const int* in_sizes, int n_in,
                              void* d_out, int out_size) {
    const float* h   = (const float*)d_in[0];
    const void*  ei  = d_in[1];
    const float* ea  = (const float*)d_in[2];
    const float* We1 = (const float*)d_in[3];
    const float* be1 = (const float*)d_in[4];
    const float* We2 = (const float*)d_in[5];
    const float* be2 = (const float*)d_in[6];
    const float* Wh1 = (const float*)d_in[7];
    const float* bh1 = (const float*)d_in[8];
    const float* Wh2 = (const float*)d_in[9];
    const float* bh2 = (const float*)d_in[10];
    float* out = (float*)d_out;

    cudaFuncSetAttribute(edge_kernel_p, cudaFuncAttributeMaxDynamicSharedMemorySize, EDGE_SMEM);
    cudaFuncSetAttribute(gemm_P, cudaFuncAttributeMaxDynamicSharedMemorySize, GP_SMEM);
    cudaFuncSetAttribute(node_kernel_m, cudaFuncAttributeMaxDynamicSharedMemorySize, NODE_SMEM);

    convert_kernel<<<(N_EDGES + 255) / 256, 256>>>(ei);
    prep_kernel<<<64, 256>>>(We1, We2, Wh1, Wh2);
    gemm_P<<<(N_NODES + 127) / 128, 256, GP_SMEM>>>(h);
    edge_kernel_p<<<NSM, 256, EDGE_SMEM>>>(ea, be1, be2);
    node_kernel_m<<<(N_NODES + 63) / 64, 256, NODE_SMEM>>>(h, bh1, bh2, out);
}

// round 10
// speedup vs baseline: 1.0713x; 1.0713x over previous
#include <cuda_runtime.h>
#include <cstdint>

#define N_NODES 50000
#define N_EDGES 800000
#define DNODE   128
#define DEDGE   32
#define HID     128

typedef unsigned long long u64;

// ---------------- device-global scratch (no allocations allowed) ----------------
__device__ int   g_src[N_EDGES];
__device__ int   g_dst[N_EDGES];
__device__ float g_mi[(size_t)N_NODES * HID];      // 25.6 MB scatter target
__device__ float g_P[(size_t)N_NODES * 256];       // 51.2 MB: [h@W1a | h@W1b]
__device__ float g_W1r[288 * 128];                 // We1, tf32-rounded (RNA), [K][N]
__device__ float g_W2r[128 * 128];                 // We2, tf32-rounded (RNA), [K][N]
__device__ float g_Wh1hi[256 * 128];               // Wh1 split hi/lo (3xTF32)
__device__ float g_Wh1lo[256 * 128];
__device__ float g_Wh2hi[128 * 128];
__device__ float g_Wh2lo[128 * 128];

// ---------------- helpers ----------------
__device__ __forceinline__ uint32_t smem_u32(const void* p) {
    uint32_t a;
    asm("{ .reg .u64 t; cvta.to.shared.u64 t, %1; cvt.u32.u64 %0, t; }" : "=r"(a) : "l"(p));
    return a;
}
__device__ __forceinline__ uint32_t rna(float x) {
    uint32_t r; asm("cvt.rna.tf32.f32 %0, %1;" : "=r"(r) : "f"(x)); return r;
}

#define CP_ASYNC(ds, gp) \
    asm volatile("cp.async.cg.shared.global [%0], [%1], 16;" :: "r"(ds), "l"(gp))
#define CP_COMMIT() asm volatile("cp.async.commit_group;" ::: "memory")
#define CP_WAIT1()  asm volatile("cp.async.wait_group 1;" ::: "memory")
#define CP_WAIT0()  asm volatile("cp.async.wait_group 0;" ::: "memory")

#define MMA_TF32(C, a0, a1, a2, a3, b0, b1) \
    asm volatile("mma.sync.aligned.m16n8k8.row.col.f32.tf32.tf32.f32 " \
        "{%0,%1,%2,%3}, {%4,%5,%6,%7}, {%8,%9}, {%0,%1,%2,%3};" \
        : "+f"((C)[0]), "+f"((C)[1]), "+f"((C)[2]), "+f"((C)[3]) \
        : "r"(a0), "r"(a1), "r"(a2), "r"(a3), "r"(b0), "r"(b1))

// ---------------- aux kernel: dtype-detect + index convert + zero g_mi ----------------
__global__ void convert_kernel(const void* __restrict__ ei) {
    __shared__ int s64;
    if (threadIdx.x == 0) {
        const int* p = (const int*)ei;
        int all0 = 1;
        for (int s = 0; s < 256; s++)
            if (p[2 * s + 1] != 0) { all0 = 0; break; }
        s64 = all0;
    }
    __syncthreads();
    int i = blockIdx.x * blockDim.x + threadIdx.x;
    if (i < N_EDGES) {
        if (s64) {
            const long long* p = (const long long*)ei;
            g_src[i] = (int)p[i];
            g_dst[i] = (int)p[N_EDGES + i];
        } else {
            const int* p = (const int*)ei;
            g_src[i] = p[i];
            g_dst[i] = p[N_EDGES + i];
        }
    }
    size_t n4 = (size_t)N_NODES * HID / 4;
    float4 z = make_float4(0.f, 0.f, 0.f, 0.f);
    for (size_t j = (size_t)blockIdx.x * blockDim.x + threadIdx.x; j < n4;
         j += (size_t)gridDim.x * blockDim.x)
        ((float4*)g_mi)[j] = z;
}

// ---------------- prep: RNA-round edge weights, split node weights hi/lo ----------------
__global__ void prep_kernel(const float* __restrict__ W1, const float* __restrict__ W2,
                            const float* __restrict__ Wh1, const float* __restrict__ Wh2) {
    int t = blockIdx.x * blockDim.x + threadIdx.x;
    int stride = gridDim.x * blockDim.x;
    for (int i = t; i < 288 * 128; i += stride)
        g_W1r[i] = __uint_as_float(rna(W1[i]));
    for (int i = t; i < 128 * 128; i += stride)
        g_W2r[i] = __uint_as_float(rna(W2[i]));
    for (int i = t; i < 256 * 128; i += stride) {
        float w = Wh1[i];
        uint32_t hi = rna(w);
        g_Wh1hi[i] = __uint_as_float(hi);
        g_Wh1lo[i] = __uint_as_float(rna(w - __uint_as_float(hi)));
    }
    for (int i = t; i < 128 * 128; i += stride) {
        float w = Wh2[i];
        uint32_t hi = rna(w);
        g_Wh2hi[i] = __uint_as_float(hi);
        g_Wh2lo[i] = __uint_as_float(rna(w - __uint_as_float(hi)));
    }
}

// =================================================================
// Precompute P = h @ [We1_a | We1_b]  (50k x 128 x 256, tf32 mma)
// =================================================================
#define GP_SMEM 98304

__global__ __launch_bounds__(256) void gemm_P(const float* __restrict__ h) {
    extern __shared__ char sm[];
    const uint32_t smb = smem_u32(sm);
    const int tid = threadIdx.x, lane = tid & 31, wid = tid >> 5;
    const int g = lane >> 2, t4 = lane & 3;
    const int m0 = (wid >> 2) * 64, n0 = (wid & 3) * 64;
    const int r0 = blockIdx.x * 128;

    auto issue_x = [&](int ch, int b) {
        uint32_t xb = smb + b * 16384;
#pragma unroll
        for (int i = 0; i < 4; i++) {
            int f = tid + i * 256;
            int row = f >> 3, q = f & 7;
            int gr = r0 + row; if (gr >= N_NODES) gr = 0;
            const float* gp = h + (size_t)gr * DNODE + ch * 32 + q * 4;
            uint32_t ds = xb + 4u * (uint32_t)(row * 32 + ((4 * q) ^ (4 * (row & 7))));
            CP_ASYNC(ds, gp);
        }
    };
    auto issue_w = [&](int ch, int b) {
        uint32_t wb = smb + 32768 + b * 32768;
#pragma unroll
        for (int i = 0; i < 8; i++) {
            int f = tid + i * 256;
            int k = f >> 6, n4 = f & 63;
            int n = 4 * n4;
            const float* gp = (n < 128)
                ? g_W1r + (size_t)(ch * 32 + k) * 128 + n
                : g_W1r + (size_t)(128 + ch * 32 + k) * 128 + (n - 128);
            uint32_t ds = wb + 4u * (uint32_t)(k * 256 + (n ^ (8 * (k & 3))));
            CP_ASYNC(ds, gp);
        }
    };

    float c[4][8][4];
#pragma unroll
    for (int mf = 0; mf < 4; mf++)
#pragma unroll
        for (int nf = 0; nf < 8; nf++)
#pragma unroll
            for (int j = 0; j < 4; j++) c[mf][nf][j] = 0.0f;

    issue_x(0, 0); issue_w(0, 0); CP_COMMIT();
    for (int ch = 0; ch < 4; ch++) {
        if (ch < 3) {
            issue_x(ch + 1, (ch + 1) & 1);
            issue_w(ch + 1, (ch + 1) & 1);
            CP_COMMIT(); CP_WAIT1();
        } else CP_WAIT0();
        __syncthreads();
        const uint32_t* Xw = (const uint32_t*)sm + (ch & 1) * 4096;
        const uint32_t* Ww = (const uint32_t*)(sm + 32768) + (ch & 1) * 8192;
#pragma unroll
        for (int s = 0; s < 4; s++) {
            const int kb = 8 * s + t4;
            uint32_t b0r[8], b1r[8];
#pragma unroll
            for (int nf = 0; nf < 8; nf++) {
                int wc = (n0 + 8 * nf + g) ^ (8 * t4);
                b0r[nf] = Ww[kb * 256 + wc];
                b1r[nf] = Ww[(kb + 4) * 256 + wc];
            }
#pragma unroll
            for (int mf = 0; mf < 4; mf++) {
                int base = (m0 + mf * 16 + g) * 32;
                uint32_t a0 = Xw[base + (kb ^ (4 * g))];
                uint32_t a1 = Xw[base + 8 * 32 + (kb ^ (4 * g))];
                uint32_t a2 = Xw[base + ((kb + 4) ^ (4 * g))];
                uint32_t a3 = Xw[base + 8 * 32 + ((kb + 4) ^ (4 * g))];
#pragma unroll
                for (int nf = 0; nf < 8; nf++)
                    MMA_TF32(c[mf][nf], a0, a1, a2, a3, b0r[nf], b1r[nf]);
            }
        }
        __syncthreads();
    }

#pragma unroll
    for (int mf = 0; mf < 4; mf++) {
        int r = m0 + mf * 16 + g;
#pragma unroll
        for (int nf = 0; nf < 8; nf++) {
            int col = n0 + 8 * nf + 2 * t4;
            if (r0 + r < N_NODES)
                *(float2*)(g_P + (size_t)(r0 + r) * 256 + col) =
                    make_float2(c[mf][nf][0], c[mf][nf][1]);
            if (r0 + r + 8 < N_NODES)
                *(float2*)(g_P + (size_t)(r0 + r + 8) * 256 + col) =
                    make_float2(c[mf][nf][2], c[mf][nf][3]);
        }
    }
}

// =================================================================
// Edge kernel v6: R6 geometry (128 edges/block, 2 CTAs/SM) with the
// P-merge and final scatter fused into registers — Ys written ONCE.
// smem: Ys 64KB @0 (ea X-chunk overlays [0,16384)), W 2x16KB @65536,
//       sb1@98304, sb2@98816, sSrc@99328, sDst@99840
// =================================================================
#define EDGE_SMEM 100352

__global__ __launch_bounds__(256, 2) void edge_kernel_m(
    const float* __restrict__ ea,
    const float* __restrict__ b1g, const float* __restrict__ b2g)
{
    extern __shared__ char sm[];
    const uint32_t smb = smem_u32(sm);
    float* Ys  = (float*)sm;
    float* sb1 = (float*)(sm + 98304);
    float* sb2 = (float*)(sm + 98816);
    int*   sSrc = (int*)(sm + 99328);
    int*   sDst = (int*)(sm + 99840);

    const int tid  = threadIdx.x;
    const int lane = tid & 31, wid = tid >> 5;
    const int g    = lane >> 2, t4 = lane & 3;
    const int m0   = (wid >> 1) * 32;
    const int n0   = (wid & 1) * 64;
    const int e0   = blockIdx.x * 128;

    if (tid < 128) {
        sb1[tid] = b1g[tid];
        sb2[tid] = b2g[tid];
        sSrc[tid] = g_src[e0 + tid];
        sDst[tid] = g_dst[e0 + tid];
    }

    // stage ea chunk (128 rows x 32 floats) into X region [0,16384)
#pragma unroll
    for (int i = 0; i < 4; i++) {
        int f = tid + i * 256;
        int row = f >> 3, q = f & 7;
        const float* gp = ea + (size_t)(e0 + row) * DEDGE + q * 4;
        uint32_t ds = smb + 4u * (uint32_t)(row * 32 + ((4 * q) ^ (4 * (row & 7))));
        CP_ASYNC(ds, gp);
    }
    auto issue_w = [&](const float* W, int ch, int wb) {
        uint32_t wbase = smb + 65536 + wb * 16384;
#pragma unroll
        for (int i = 0; i < 4; i++) {
            int f = tid + i * 256;
            int k = f >> 5, n4 = f & 31;
            const float* gp = W + (size_t)(ch * 32 + k) * 128 + n4 * 4;
            uint32_t ds = wbase + 4u * (uint32_t)(k * 128 + ((4 * n4) ^ (8 * (k & 3))));
            CP_ASYNC(ds, gp);
        }
    };
    issue_w(g_W1r, 8, 0);   // We1 rows 256..287 (edge-attr slice)
    CP_COMMIT();

    float c[2][8][4];
#pragma unroll
    for (int mf = 0; mf < 2; mf++)
#pragma unroll
        for (int nf = 0; nf < 8; nf++)
#pragma unroll
            for (int j = 0; j < 4; j++) c[mf][nf][j] = 0.0f;

    auto compute = [&](const uint32_t* Xw, int rstride, int cofs, const uint32_t* Ww) {
#pragma unroll
        for (int s = 0; s < 4; s++) {
            const int kb = 8 * s + t4;
            uint32_t b0r[8], b1r[8];
#pragma unroll
            for (int nf = 0; nf < 8; nf++) {
                int wc = (n0 + 8 * nf + g) ^ (8 * t4);
                b0r[nf] = Ww[kb * 128 + wc];
                b1r[nf] = Ww[(kb + 4) * 128 + wc];
            }
#pragma unroll
            for (int mf = 0; mf < 2; mf++) {
                int base = (m0 + mf * 16 + g) * rstride + cofs;
                uint32_t a0 = Xw[base + (kb ^ (4 * g))];
                uint32_t a1 = Xw[base + 8 * rstride + (kb ^ (4 * g))];
                uint32_t a2 = Xw[base + ((kb + 4) ^ (4 * g))];
                uint32_t a3 = Xw[base + 8 * rstride + ((kb + 4) ^ (4 * g))];
#pragma unroll
                for (int nf = 0; nf < 8; nf++)
                    MMA_TF32(c[mf][nf], a0, a1, a2, a3, b0r[nf], b1r[nf]);
            }
        }
    };

    // ======== phase 1: T = ea @ We1_e (single K=32 chunk) ========
    CP_WAIT0();
    __syncthreads();
    compute((const uint32_t*)sm, 32, 0, (const uint32_t*)(sm + 65536));
    __syncthreads();   // all warps done reading Xe/W1e before Ys write / Wbuf0 reuse

    // prefetch W2 chunk 0 — overlaps the P-gather latency below
    issue_w(g_W2r, 0, 0); CP_COMMIT();

    // ---- fused P-merge in registers: Y = relu(T + P[src].lo + P[dst].hi + b1) ----
#pragma unroll
    for (int mf = 0; mf < 2; mf++) {
        int r0r = m0 + mf * 16 + g;
        int r1r = r0r + 8;
        const float* Ps0 = g_P + (size_t)sSrc[r0r] * 256;
        const float* Pd0 = g_P + (size_t)sDst[r0r] * 256 + 128;
        const float* Ps1 = g_P + (size_t)sSrc[r1r] * 256;
        const float* Pd1 = g_P + (size_t)sDst[r1r] * 256 + 128;
#pragma unroll
        for (int nf = 0; nf < 8; nf++) {
            int cc = n0 + 8 * nf + 2 * t4;
            float2 ps0 = *(const float2*)(Ps0 + cc);
            float2 pd0 = *(const float2*)(Pd0 + cc);
            float2 ps1 = *(const float2*)(Ps1 + cc);
            float2 pd1 = *(const float2*)(Pd1 + cc);
            float bb0 = sb1[cc], bb1 = sb1[cc + 1];
            int w = (cc & ~31) + ((cc & 31) ^ (4 * g));
            float2 y0, y1;
            y0.x = fmaxf(c[mf][nf][0] + ps0.x + pd0.x + bb0, 0.0f);
            y0.y = fmaxf(c[mf][nf][1] + ps0.y + pd0.y + bb1, 0.0f);
            y1.x = fmaxf(c[mf][nf][2] + ps1.x + pd1.x + bb0, 0.0f);
            y1.y = fmaxf(c[mf][nf][3] + ps1.y + pd1.y + bb1, 0.0f);
            *(float2*)&Ys[r0r * 128 + w] = y0;
            *(float2*)&Ys[r1r * 128 + w] = y1;
            c[mf][nf][0] = 0.0f; c[mf][nf][1] = 0.0f;
            c[mf][nf][2] = 0.0f; c[mf][nf][3] = 0.0f;
        }
    }
    __syncthreads();   // Ys complete before phase 2 reads

    // ======== phase 2: layer 2, K=128, W double-buffered ========
    for (int ch = 0; ch < 4; ch++) {
        if (ch < 3) {
            issue_w(g_W2r, ch + 1, (ch + 1) & 1);
            CP_COMMIT(); CP_WAIT1();
        } else CP_WAIT0();
        __syncthreads();
        compute((const uint32_t*)sm, 128, ch * 32,
                (const uint32_t*)(sm + 65536) + (ch & 1) * 4096);
        if (ch < 3) __syncthreads();
    }

    // ---- fused scatter: red.v2 straight from accumulators (+b2) ----
#pragma unroll
    for (int mf = 0; mf < 2; mf++) {
        int r0r = m0 + mf * 16 + g;
        int r1r = r0r + 8;
        float* gd0 = g_mi + (size_t)sDst[r0r] * HID;
        float* gd1 = g_mi + (size_t)sDst[r1r] * HID;
#pragma unroll
        for (int nf = 0; nf < 8; nf++) {
            int cc = n0 + 8 * nf + 2 * t4;
            float bb0 = sb2[cc], bb1 = sb2[cc + 1];
            asm volatile("red.global.add.v2.f32 [%0], {%1,%2};"
                         :: "l"(gd0 + cc),
                            "f"(c[mf][nf][0] + bb0), "f"(c[mf][nf][1] + bb1) : "memory");
            asm volatile("red.global.add.v2.f32 [%0], {%1,%2};"
                         :: "l"(gd1 + cc),
                            "f"(c[mf][nf][2] + bb0), "f"(c[mf][nf][3] + bb1) : "memory");
        }
    }
}

// =================================================================
// Node MLP via 3xTF32 split mma (unchanged from R6)
// =================================================================
#define NODE_SMEM 99328

__global__ __launch_bounds__(256, 2) void node_kernel_m(
    const float* __restrict__ h,
    const float* __restrict__ b1g, const float* __restrict__ b2g,
    float* __restrict__ out)
{
    extern __shared__ char sm[];
    const uint32_t smb = smem_u32(sm);
    float* Ys  = (float*)sm;
    float* sb1 = (float*)(sm + 98304);
    float* sb2 = (float*)(sm + 98816);

    const int tid  = threadIdx.x;
    const int lane = tid & 31, wid = tid >> 5;
    const int g    = lane >> 2, t4 = lane & 3;
    const int m0   = (wid >> 1) * 16;
    const int n0   = (wid & 1) * 64;
    const int r0   = blockIdx.x * 64;

    if (tid < 128) { sb1[tid] = b1g[tid]; sb2[tid] = b2g[tid]; }

    auto issue_x = [&](int ch, int b) {
        uint32_t xb = smb + b * 8192;
#pragma unroll
        for (int i = 0; i < 2; i++) {
            int f = tid + i * 256;
            int row = f >> 3, q = f & 7;
            int gr = r0 + row; if (gr >= N_NODES) gr = 0;
            const float* gp = (ch < 4)
                ? h    + (size_t)gr * DNODE + ch * 32 + q * 4
                : g_mi + (size_t)gr * HID   + (ch - 4) * 32 + q * 4;
            uint32_t ds = xb + 4u * (uint32_t)(row * 32 + ((4 * q) ^ (4 * (row & 7))));
            CP_ASYNC(ds, gp);
        }
    };
    auto issue_w = [&](const float* Whi, const float* Wlo, int ch, int b) {
        uint32_t base_hi = smb + 32768 + b * 32768;
#pragma unroll
        for (int i = 0; i < 4; i++) {
            int f = tid + i * 256;
            int k = f >> 5, n4 = f & 31;
            uint32_t off = 4u * (uint32_t)(k * 128 + ((4 * n4) ^ (8 * (k & 3))));
            CP_ASYNC(base_hi + off,         Whi + (size_t)(ch * 32 + k) * 128 + n4 * 4);
            CP_ASYNC(base_hi + 16384 + off, Wlo + (size_t)(ch * 32 + k) * 128 + n4 * 4);
        }
    };

    float c[8][4];
#pragma unroll
    for (int nf = 0; nf < 8; nf++)
#pragma unroll
        for (int j = 0; j < 4; j++) c[nf][j] = 0.0f;

    auto computeN = [&](const uint32_t* Xw, int rstride, int cofs,
                        const uint32_t* Whi, const uint32_t* Wlo) {
#pragma unroll
        for (int s = 0; s < 4; s++) {
            const int kb = 8 * s + t4;
            int base0 = (m0 + g) * rstride + cofs;
            int base1 = (m0 + 8 + g) * rstride + cofs;
            float x0 = __uint_as_float(Xw[base0 + (kb ^ (4 * g))]);
            float x1 = __uint_as_float(Xw[base1 + (kb ^ (4 * g))]);
            float x2 = __uint_as_float(Xw[base0 + ((kb + 4) ^ (4 * g))]);
            float x3 = __uint_as_float(Xw[base1 + ((kb + 4) ^ (4 * g))]);
            uint32_t h0 = rna(x0), h1 = rna(x1), h2 = rna(x2), h3 = rna(x3);
            uint32_t l0 = rna(x0 - __uint_as_float(h0));
            uint32_t l1 = rna(x1 - __uint_as_float(h1));
            uint32_t l2 = rna(x2 - __uint_as_float(h2));
            uint32_t l3 = rna(x3 - __uint_as_float(h3));
#pragma unroll
            for (int nf = 0; nf < 8; nf++) {
                int wc = (n0 + 8 * nf + g) ^ (8 * t4);
                uint32_t bh0 = Whi[kb * 128 + wc], bh1 = Whi[(kb + 4) * 128 + wc];
                uint32_t bl0 = Wlo[kb * 128 + wc], bl1 = Wlo[(kb + 4) * 128 + wc];
                MMA_TF32(c[nf], h0, h1, h2, h3, bh0, bh1);
                MMA_TF32(c[nf], l0, l1, l2, l3, bh0, bh1);
                MMA_TF32(c[nf], h0, h1, h2, h3, bl0, bl1);
            }
        }
    };

    issue_x(0, 0); issue_w(g_Wh1hi, g_Wh1lo, 0, 0); CP_COMMIT();
    for (int ch = 0; ch < 8; ch++) {
        if (ch < 7) {
            issue_x(ch + 1, (ch + 1) & 1);
            issue_w(g_Wh1hi, g_Wh1lo, ch + 1, (ch + 1) & 1);
            CP_COMMIT(); CP_WAIT1();
        } else CP_WAIT0();
        __syncthreads();
        computeN((const uint32_t*)sm + (ch & 1) * 2048, 32, 0,
                 (const uint32_t*)(sm + 32768 + (ch & 1) * 32768),
                 (const uint32_t*)(sm + 32768 + (ch & 1) * 32768 + 16384));
        __syncthreads();
    }

#pragma unroll
    for (int nf = 0; nf < 8; nf++) {
        int cc = n0 + 8 * nf + 2 * t4;
        float bb0 = sb1[cc], bb1 = sb1[cc + 1];
        int w = (cc & ~31) + ((cc & 31) ^ (4 * g));
        *(float2*)&Ys[(m0 + g) * 128 + w] =
            make_float2(fmaxf(c[nf][0] + bb0, 0.0f), fmaxf(c[nf][1] + bb1, 0.0f));
        *(float2*)&Ys[(m0 + 8 + g) * 128 + w] =
            make_float2(fmaxf(c[nf][2] + bb0, 0.0f), fmaxf(c[nf][3] + bb1, 0.0f));
#pragma unroll
        for (int j = 0; j < 4; j++) c[nf][j] = 0.0f;
    }
    issue_w(g_Wh2hi, g_Wh2lo, 0, 0); CP_COMMIT();
    __syncthreads();

    for (int ch = 0; ch < 4; ch++) {
        if (ch < 3) {
            issue_w(g_Wh2hi, g_Wh2lo, ch + 1, (ch + 1) & 1);
            CP_COMMIT(); CP_WAIT1();
        } else CP_WAIT0();
        __syncthreads();
        computeN((const uint32_t*)sm, 128, ch * 32,
                 (const uint32_t*)(sm + 32768 + (ch & 1) * 32768),
                 (const uint32_t*)(sm + 32768 + (ch & 1) * 32768 + 16384));
        __syncthreads();
    }

#pragma unroll
    for (int nf = 0; nf < 8; nf++) {
        int cc = n0 + 8 * nf + 2 * t4;
        float bb0 = sb2[cc], bb1 = sb2[cc + 1];
        int ra = r0 + m0 + g, rb = ra + 8;
        if (ra < N_NODES)
            *(float2*)(out + (size_t)ra * 128 + cc) =
                make_float2(c[nf][0] + bb0, c[nf][1] + bb1);
        if (rb < N_NODES)
            *(float2*)(out + (size_t)rb * 128 + cc) =
                make_float2(c[nf][2] + bb0, c[nf][3] + bb1);
    }
}

// =================================================================
extern "C" void kernel_launch(void* const* d_in, const int* in_sizes, int n_in,
                              void* d_out, int out_size) {
    const float* h   = (const float*)d_in[0];
    const void*  ei  = d_in[1];
    const float* ea  = (const float*)d_in[2];
    const float* We1 = (const float*)d_in[3];
    const float* be1 = (const float*)d_in[4];
    const float* We2 = (const float*)d_in[5];
    const float* be2 = (const float*)d_in[6];
    const float* Wh1 = (const float*)d_in[7];
    const float* bh1 = (const float*)d_in[8];
    const float* Wh2 = (const float*)d_in[9];
    const float* bh2 = (const float*)d_in[10];
    float* out = (float*)d_out;

    cudaFuncSetAttribute(edge_kernel_m, cudaFuncAttributeMaxDynamicSharedMemorySize, EDGE_SMEM);
    cudaFuncSetAttribute(gemm_P, cudaFuncAttributeMaxDynamicSharedMemorySize, GP_SMEM);
    cudaFuncSetAttribute(node_kernel_m, cudaFuncAttributeMaxDynamicSharedMemorySize, NODE_SMEM);

    convert_kernel<<<(N_EDGES + 255) / 256, 256>>>(ei);
    prep_kernel<<<64, 256>>>(We1, We2, Wh1, Wh2);
    gemm_P<<<(N_NODES + 127) / 128, 256, GP_SMEM>>>(h);
    edge_kernel_m<<<N_EDGES / 128, 256, EDGE_SMEM>>>(ea, be1, be2);
    node_kernel_m<<<(N_NODES + 63) / 64, 256, NODE_SMEM>>>(h, bh1, bh2, out);
}

// round 11
// speedup vs baseline: 1.2598x; 1.1760x over previous
#include <cuda_runtime.h>
#include <cstdint>

#define N_NODES 50000
#define N_EDGES 800000
#define DNODE   128
#define DEDGE   32
#define HID     128

typedef unsigned long long u64;

// ---------------- device-global scratch (no allocations allowed) ----------------
__device__ int   g_src[N_EDGES];
__device__ int   g_dst[N_EDGES];
__device__ float g_mi[(size_t)N_NODES * HID];      // 25.6 MB scatter target
__device__ float g_P[(size_t)N_NODES * 256];       // 51.2 MB: [h@W1a | h@W1b]
__device__ float g_W1r[288 * 128];                 // We1, tf32-rounded (RNA), [K][N]
__device__ float g_W2r[128 * 128];                 // We2, tf32-rounded (RNA), [K][N]
__device__ float g_Wh1hi[256 * 128];               // Wh1 split hi/lo (3xTF32)
__device__ float g_Wh1lo[256 * 128];
__device__ float g_Wh2hi[128 * 128];
__device__ float g_Wh2lo[128 * 128];

// ---------------- helpers ----------------
__device__ __forceinline__ uint32_t smem_u32(const void* p) {
    uint32_t a;
    asm("{ .reg .u64 t; cvta.to.shared.u64 t, %1; cvt.u32.u64 %0, t; }" : "=r"(a) : "l"(p));
    return a;
}
__device__ __forceinline__ uint32_t rna(float x) {
    uint32_t r; asm("cvt.rna.tf32.f32 %0, %1;" : "=r"(r) : "f"(x)); return r;
}

#define CP_ASYNC(ds, gp) \
    asm volatile("cp.async.cg.shared.global [%0], [%1], 16;" :: "r"(ds), "l"(gp))
#define CP_COMMIT() asm volatile("cp.async.commit_group;" ::: "memory")
#define CP_WAIT1()  asm volatile("cp.async.wait_group 1;" ::: "memory")
#define CP_WAIT0()  asm volatile("cp.async.wait_group 0;" ::: "memory")

#define MMA_TF32(C, a0, a1, a2, a3, b0, b1) \
    asm volatile("mma.sync.aligned.m16n8k8.row.col.f32.tf32.tf32.f32 " \
        "{%0,%1,%2,%3}, {%4,%5,%6,%7}, {%8,%9}, {%0,%1,%2,%3};" \
        : "+f"((C)[0]), "+f"((C)[1]), "+f"((C)[2]), "+f"((C)[3]) \
        : "r"(a0), "r"(a1), "r"(a2), "r"(a3), "r"(b0), "r"(b1))

// ---------------- aux kernel: dtype-detect + index convert + zero g_mi ----------------
__global__ void convert_kernel(const void* __restrict__ ei) {
    __shared__ int s64;
    if (threadIdx.x == 0) {
        const int* p = (const int*)ei;
        int all0 = 1;
        for (int s = 0; s < 256; s++)
            if (p[2 * s + 1] != 0) { all0 = 0; break; }
        s64 = all0;
    }
    __syncthreads();
    int i = blockIdx.x * blockDim.x + threadIdx.x;
    if (i < N_EDGES) {
        if (s64) {
            const long long* p = (const long long*)ei;
            g_src[i] = (int)p[i];
            g_dst[i] = (int)p[N_EDGES + i];
        } else {
            const int* p = (const int*)ei;
            g_src[i] = p[i];
            g_dst[i] = p[N_EDGES + i];
        }
    }
    size_t n4 = (size_t)N_NODES * HID / 4;
    float4 z = make_float4(0.f, 0.f, 0.f, 0.f);
    for (size_t j = (size_t)blockIdx.x * blockDim.x + threadIdx.x; j < n4;
         j += (size_t)gridDim.x * blockDim.x)
        ((float4*)g_mi)[j] = z;
}

// ---------------- prep: RNA-round edge weights, split node weights hi/lo ----------------
__global__ void prep_kernel(const float* __restrict__ W1, const float* __restrict__ W2,
                            const float* __restrict__ Wh1, const float* __restrict__ Wh2) {
    int t = blockIdx.x * blockDim.x + threadIdx.x;
    int stride = gridDim.x * blockDim.x;
    for (int i = t; i < 288 * 128; i += stride)
        g_W1r[i] = __uint_as_float(rna(W1[i]));
    for (int i = t; i < 128 * 128; i += stride)
        g_W2r[i] = __uint_as_float(rna(W2[i]));
    for (int i = t; i < 256 * 128; i += stride) {
        float w = Wh1[i];
        uint32_t hi = rna(w);
        g_Wh1hi[i] = __uint_as_float(hi);
        g_Wh1lo[i] = __uint_as_float(rna(w - __uint_as_float(hi)));
    }
    for (int i = t; i < 128 * 128; i += stride) {
        float w = Wh2[i];
        uint32_t hi = rna(w);
        g_Wh2hi[i] = __uint_as_float(hi);
        g_Wh2lo[i] = __uint_as_float(rna(w - __uint_as_float(hi)));
    }
}

// =================================================================
// Precompute P = h @ [We1_a | We1_b]  (50k x 128 x 256, tf32 mma)
// =================================================================
#define GP_SMEM 98304

__global__ __launch_bounds__(256) void gemm_P(const float* __restrict__ h) {
    extern __shared__ char sm[];
    const uint32_t smb = smem_u32(sm);
    const int tid = threadIdx.x, lane = tid & 31, wid = tid >> 5;
    const int g = lane >> 2, t4 = lane & 3;
    const int m0 = (wid >> 2) * 64, n0 = (wid & 3) * 64;
    const int r0 = blockIdx.x * 128;

    auto issue_x = [&](int ch, int b) {
        uint32_t xb = smb + b * 16384;
#pragma unroll
        for (int i = 0; i < 4; i++) {
            int f = tid + i * 256;
            int row = f >> 3, q = f & 7;
            int gr = r0 + row; if (gr >= N_NODES) gr = 0;
            const float* gp = h + (size_t)gr * DNODE + ch * 32 + q * 4;
            uint32_t ds = xb + 4u * (uint32_t)(row * 32 + ((4 * q) ^ (4 * (row & 7))));
            CP_ASYNC(ds, gp);
        }
    };
    auto issue_w = [&](int ch, int b) {
        uint32_t wb = smb + 32768 + b * 32768;
#pragma unroll
        for (int i = 0; i < 8; i++) {
            int f = tid + i * 256;
            int k = f >> 6, n4 = f & 63;
            int n = 4 * n4;
            const float* gp = (n < 128)
                ? g_W1r + (size_t)(ch * 32 + k) * 128 + n
                : g_W1r + (size_t)(128 + ch * 32 + k) * 128 + (n - 128);
            uint32_t ds = wb + 4u * (uint32_t)(k * 256 + (n ^ (8 * (k & 3))));
            CP_ASYNC(ds, gp);
        }
    };

    float c[4][8][4];
#pragma unroll
    for (int mf = 0; mf < 4; mf++)
#pragma unroll
        for (int nf = 0; nf < 8; nf++)
#pragma unroll
            for (int j = 0; j < 4; j++) c[mf][nf][j] = 0.0f;

    issue_x(0, 0); issue_w(0, 0); CP_COMMIT();
    for (int ch = 0; ch < 4; ch++) {
        CP_WAIT0();
        __syncthreads();
        if (ch < 3) {
            issue_x(ch + 1, (ch + 1) & 1);
            issue_w(ch + 1, (ch + 1) & 1);
            CP_COMMIT();
        }
        const uint32_t* Xw = (const uint32_t*)sm + (ch & 1) * 4096;
        const uint32_t* Ww = (const uint32_t*)(sm + 32768) + (ch & 1) * 8192;
#pragma unroll
        for (int s = 0; s < 4; s++) {
            const int kb = 8 * s + t4;
            uint32_t b0r[8], b1r[8];
#pragma unroll
            for (int nf = 0; nf < 8; nf++) {
                int wc = (n0 + 8 * nf + g) ^ (8 * t4);
                b0r[nf] = Ww[kb * 256 + wc];
                b1r[nf] = Ww[(kb + 4) * 256 + wc];
            }
#pragma unroll
            for (int mf = 0; mf < 4; mf++) {
                int base = (m0 + mf * 16 + g) * 32;
                uint32_t a0 = Xw[base + (kb ^ (4 * g))];
                uint32_t a1 = Xw[base + 8 * 32 + (kb ^ (4 * g))];
                uint32_t a2 = Xw[base + ((kb + 4) ^ (4 * g))];
                uint32_t a3 = Xw[base + 8 * 32 + ((kb + 4) ^ (4 * g))];
#pragma unroll
                for (int nf = 0; nf < 8; nf++)
                    MMA_TF32(c[mf][nf], a0, a1, a2, a3, b0r[nf], b1r[nf]);
            }
        }
    }

#pragma unroll
    for (int mf = 0; mf < 4; mf++) {
        int r = m0 + mf * 16 + g;
#pragma unroll
        for (int nf = 0; nf < 8; nf++) {
            int col = n0 + 8 * nf + 2 * t4;
            if (r0 + r < N_NODES)
                *(float2*)(g_P + (size_t)(r0 + r) * 256 + col) =
                    make_float2(c[mf][nf][0], c[mf][nf][1]);
            if (r0 + r + 8 < N_NODES)
                *(float2*)(g_P + (size_t)(r0 + r + 8) * 256 + col) =
                    make_float2(c[mf][nf][2], c[mf][nf][3]);
        }
    }
}

// =================================================================
// Edge kernel v7: R6 data movement, leaner schedule.
//   - W2 chunk0 prefetched into buf1 at kernel start
//   - one __syncthreads per pipeline chunk (WAIT -> sync -> issue -> compute)
// smem: Ys 64KB @0 (ea X-chunk overlays [0,16384)), W 2x16KB @65536,
//       sb1@98304, sb2@98816, sSrc@99328, sDst@99840
// =================================================================
#define EDGE_SMEM 100352

__global__ __launch_bounds__(256, 2) void edge_kernel_m(
    const float* __restrict__ ea,
    const float* __restrict__ b1g, const float* __restrict__ b2g)
{
    extern __shared__ char sm[];
    const uint32_t smb = smem_u32(sm);
    float* Ys  = (float*)sm;
    float* sb1 = (float*)(sm + 98304);
    float* sb2 = (float*)(sm + 98816);
    int*   sSrc = (int*)(sm + 99328);
    int*   sDst = (int*)(sm + 99840);

    const int tid  = threadIdx.x;
    const int lane = tid & 31, wid = tid >> 5;
    const int g    = lane >> 2, t4 = lane & 3;
    const int m0   = (wid >> 1) * 32;
    const int n0   = (wid & 1) * 64;
    const int e0   = blockIdx.x * 128;

    if (tid < 128) {
        sb1[tid] = b1g[tid];
        sb2[tid] = b2g[tid];
        sSrc[tid] = g_src[e0 + tid];
        sDst[tid] = g_dst[e0 + tid];
    }

    auto issue_w = [&](const float* W, int ch, int wb) {
        uint32_t wbase = smb + 65536 + wb * 16384;
#pragma unroll
        for (int i = 0; i < 4; i++) {
            int f = tid + i * 256;
            int k = f >> 5, n4 = f & 31;
            const float* gp = W + (size_t)(ch * 32 + k) * 128 + n4 * 4;
            uint32_t ds = wbase + 4u * (uint32_t)(k * 128 + ((4 * n4) ^ (8 * (k & 3))));
            CP_ASYNC(ds, gp);
        }
    };

    // group A: ea chunk + W1e (buf0)
#pragma unroll
    for (int i = 0; i < 4; i++) {
        int f = tid + i * 256;
        int row = f >> 3, q = f & 7;
        const float* gp = ea + (size_t)(e0 + row) * DEDGE + q * 4;
        uint32_t ds = smb + 4u * (uint32_t)(row * 32 + ((4 * q) ^ (4 * (row & 7))));
        CP_ASYNC(ds, gp);
    }
    issue_w(g_W1r, 8, 0);
    CP_COMMIT();
    // group B: W2 chunk0 (buf1) — prefetched across phase 1 + epilogue
    issue_w(g_W2r, 0, 1);
    CP_COMMIT();

    float c[2][8][4];
#pragma unroll
    for (int mf = 0; mf < 2; mf++)
#pragma unroll
        for (int nf = 0; nf < 8; nf++)
#pragma unroll
            for (int j = 0; j < 4; j++) c[mf][nf][j] = 0.0f;

    auto compute = [&](const uint32_t* Xw, int rstride, int cofs, const uint32_t* Ww) {
#pragma unroll
        for (int s = 0; s < 4; s++) {
            const int kb = 8 * s + t4;
            uint32_t b0r[8], b1r[8];
#pragma unroll
            for (int nf = 0; nf < 8; nf++) {
                int wc = (n0 + 8 * nf + g) ^ (8 * t4);
                b0r[nf] = Ww[kb * 128 + wc];
                b1r[nf] = Ww[(kb + 4) * 128 + wc];
            }
#pragma unroll
            for (int mf = 0; mf < 2; mf++) {
                int base = (m0 + mf * 16 + g) * rstride + cofs;
                uint32_t a0 = Xw[base + (kb ^ (4 * g))];
                uint32_t a1 = Xw[base + 8 * rstride + (kb ^ (4 * g))];
                uint32_t a2 = Xw[base + ((kb + 4) ^ (4 * g))];
                uint32_t a3 = Xw[base + 8 * rstride + ((kb + 4) ^ (4 * g))];
#pragma unroll
                for (int nf = 0; nf < 8; nf++)
                    MMA_TF32(c[mf][nf], a0, a1, a2, a3, b0r[nf], b1r[nf]);
            }
        }
    };

    // ======== phase 1: T = ea @ We1_e (K=32, W1e @ buf0) ========
    CP_WAIT1();                 // group A arrived (B may be in flight)
    __syncthreads();
    compute((const uint32_t*)sm, 32, 0, (const uint32_t*)(sm + 65536));
    __syncthreads();            // Xe + buf0 free

    // group C: W2 chunk1 -> buf0 (overlaps epilogue + P-merge)
    issue_w(g_W2r, 1, 0);
    CP_COMMIT();

    // epilogue A: write raw T into Ys (swizzled), zero accumulators
#pragma unroll
    for (int mf = 0; mf < 2; mf++) {
        int r0r = m0 + mf * 16 + g;
#pragma unroll
        for (int nf = 0; nf < 8; nf++) {
            int cc = n0 + 8 * nf + 2 * t4;
            int w = (cc & ~31) + ((cc & 31) ^ (4 * g));
            *(float2*)&Ys[r0r * 128 + w]       = make_float2(c[mf][nf][0], c[mf][nf][1]);
            *(float2*)&Ys[(r0r + 8) * 128 + w] = make_float2(c[mf][nf][2], c[mf][nf][3]);
#pragma unroll
            for (int j = 0; j < 4; j++) c[mf][nf][j] = 0.0f;
        }
    }
    __syncthreads();            // fragment-map writes -> row-map reads

    // P-merge: Y = relu(T + P[src].lo + P[dst].hi + b1)   (row-major float4)
#pragma unroll 4
    for (int i = 0; i < 16; i++) {
        int f = tid + i * 256;
        int row = f >> 5, c4 = f & 31;
        int w = row * 128 + (c4 >> 3) * 32 + ((4 * (c4 & 7)) ^ (4 * (row & 7)));
        float4 t = *(const float4*)&Ys[w];
        float4 ps = *(const float4*)(g_P + (size_t)sSrc[row] * 256 + 4 * c4);
        float4 pd = *(const float4*)(g_P + (size_t)sDst[row] * 256 + 128 + 4 * c4);
        float4 b = *(const float4*)&sb1[4 * c4];
        float4 y;
        y.x = fmaxf(t.x + ps.x + pd.x + b.x, 0.0f);
        y.y = fmaxf(t.y + ps.y + pd.y + b.y, 0.0f);
        y.z = fmaxf(t.z + ps.z + pd.z + b.z, 0.0f);
        y.w = fmaxf(t.w + ps.w + pd.w + b.w, 0.0f);
        *(float4*)&Ys[w] = y;
    }

    // ======== phase 2: K=128, chunks 0..3, buffers 1,0,1,0 ========
    // ch0 (buf1, group B)
    CP_WAIT1();                 // B arrived (C may pend)
    __syncthreads();            // publishes P-merge Ys + B's data; retires merge reads
    compute((const uint32_t*)sm, 128, 0, (const uint32_t*)(sm + 65536) + 4096);
    // ch1 (buf0, group C)
    CP_WAIT0();
    __syncthreads();
    issue_w(g_W2r, 2, 1); CP_COMMIT();   // group D -> buf1 (freed by sync)
    compute((const uint32_t*)sm, 128, 32, (const uint32_t*)(sm + 65536));
    // ch2 (buf1, group D)
    CP_WAIT0();
    __syncthreads();
    issue_w(g_W2r, 3, 0); CP_COMMIT();   // group E -> buf0
    compute((const uint32_t*)sm, 128, 64, (const uint32_t*)(sm + 65536) + 4096);
    // ch3 (buf0, group E)
    CP_WAIT0();
    __syncthreads();
    compute((const uint32_t*)sm, 128, 96, (const uint32_t*)(sm + 65536));
    __syncthreads();            // all warps done reading Ys

    // stage messages (+bias b2) into Ys
#pragma unroll
    for (int mf = 0; mf < 2; mf++) {
        int r0r = m0 + mf * 16 + g;
#pragma unroll
        for (int nf = 0; nf < 8; nf++) {
            int cc = n0 + 8 * nf + 2 * t4;
            float bb0 = sb2[cc], bb1 = sb2[cc + 1];
            int w = (cc & ~31) + ((cc & 31) ^ (4 * g));
            *(float2*)&Ys[r0r * 128 + w] =
                make_float2(c[mf][nf][0] + bb0, c[mf][nf][1] + bb1);
            *(float2*)&Ys[(r0r + 8) * 128 + w] =
                make_float2(c[mf][nf][2] + bb0, c[mf][nf][3] + bb1);
        }
    }
    __syncthreads();

    // coalesced vectorized scatter-add (one dst row per warp-instr)
#pragma unroll 4
    for (int i = 0; i < 16; i++) {
        int f = tid + i * 256;
        int row = f >> 5, c4 = f & 31;
        int w = row * 128 + (c4 >> 3) * 32 + ((4 * (c4 & 7)) ^ (4 * (row & 7)));
        float4 v = *(const float4*)&Ys[w];
        float* gp = g_mi + (size_t)sDst[row] * HID + 4 * c4;
        asm volatile("red.global.add.v4.f32 [%0], {%1,%2,%3,%4};"
                     :: "l"(gp), "f"(v.x), "f"(v.y), "f"(v.z), "f"(v.w) : "memory");
    }
}

// =================================================================
// Node MLP via 3xTF32 split mma — R6 math, leaner schedule
// (one sync per chunk: WAIT -> sync -> issue -> compute).
// =================================================================
#define NODE_SMEM 99328

__global__ __launch_bounds__(256, 2) void node_kernel_m(
    const float* __restrict__ h,
    const float* __restrict__ b1g, const float* __restrict__ b2g,
    float* __restrict__ out)
{
    extern __shared__ char sm[];
    const uint32_t smb = smem_u32(sm);
    float* Ys  = (float*)sm;
    float* sb1 = (float*)(sm + 98304);
    float* sb2 = (float*)(sm + 98816);

    const int tid  = threadIdx.x;
    const int lane = tid & 31, wid = tid >> 5;
    const int g    = lane >> 2, t4 = lane & 3;
    const int m0   = (wid >> 1) * 16;
    const int n0   = (wid & 1) * 64;
    const int r0   = blockIdx.x * 64;

    if (tid < 128) { sb1[tid] = b1g[tid]; sb2[tid] = b2g[tid]; }

    auto issue_x = [&](int ch, int b) {
        uint32_t xb = smb + b * 8192;
#pragma unroll
        for (int i = 0; i < 2; i++) {
            int f = tid + i * 256;
            int row = f >> 3, q = f & 7;
            int gr = r0 + row; if (gr >= N_NODES) gr = 0;
            const float* gp = (ch < 4)
                ? h    + (size_t)gr * DNODE + ch * 32 + q * 4
                : g_mi + (size_t)gr * HID   + (ch - 4) * 32 + q * 4;
            uint32_t ds = xb + 4u * (uint32_t)(row * 32 + ((4 * q) ^ (4 * (row & 7))));
            CP_ASYNC(ds, gp);
        }
    };
    auto issue_w = [&](const float* Whi, const float* Wlo, int ch, int b) {
        uint32_t base_hi = smb + 32768 + b * 32768;
#pragma unroll
        for (int i = 0; i < 4; i++) {
            int f = tid + i * 256;
            int k = f >> 5, n4 = f & 31;
            uint32_t off = 4u * (uint32_t)(k * 128 + ((4 * n4) ^ (8 * (k & 3))));
            CP_ASYNC(base_hi + off,         Whi + (size_t)(ch * 32 + k) * 128 + n4 * 4);
            CP_ASYNC(base_hi + 16384 + off, Wlo + (size_t)(ch * 32 + k) * 128 + n4 * 4);
        }
    };

    float c[8][4];
#pragma unroll
    for (int nf = 0; nf < 8; nf++)
#pragma unroll
        for (int j = 0; j < 4; j++) c[nf][j] = 0.0f;

    auto computeN = [&](const uint32_t* Xw, int rstride, int cofs,
                        const uint32_t* Whi, const uint32_t* Wlo) {
#pragma unroll
        for (int s = 0; s < 4; s++) {
            const int kb = 8 * s + t4;
            int base0 = (m0 + g) * rstride + cofs;
            int base1 = (m0 + 8 + g) * rstride + cofs;
            float x0 = __uint_as_float(Xw[base0 + (kb ^ (4 * g))]);
            float x1 = __uint_as_float(Xw[base1 + (kb ^ (4 * g))]);
            float x2 = __uint_as_float(Xw[base0 + ((kb + 4) ^ (4 * g))]);
            float x3 = __uint_as_float(Xw[base1 + ((kb + 4) ^ (4 * g))]);
            uint32_t h0 = rna(x0), h1 = rna(x1), h2 = rna(x2), h3 = rna(x3);
            uint32_t l0 = rna(x0 - __uint_as_float(h0));
            uint32_t l1 = rna(x1 - __uint_as_float(h1));
            uint32_t l2 = rna(x2 - __uint_as_float(h2));
            uint32_t l3 = rna(x3 - __uint_as_float(h3));
#pragma unroll
            for (int nf = 0; nf < 8; nf++) {
                int wc = (n0 + 8 * nf + g) ^ (8 * t4);
                uint32_t bh0 = Whi[kb * 128 + wc], bh1 = Whi[(kb + 4) * 128 + wc];
                uint32_t bl0 = Wlo[kb * 128 + wc], bl1 = Wlo[(kb + 4) * 128 + wc];
                MMA_TF32(c[nf], h0, h1, h2, h3, bh0, bh1);
                MMA_TF32(c[nf], l0, l1, l2, l3, bh0, bh1);
                MMA_TF32(c[nf], h0, h1, h2, h3, bl0, bl1);
            }
        }
    };

    // ======== layer 1: K=256, 8 chunks — one sync per chunk ========
    issue_x(0, 0); issue_w(g_Wh1hi, g_Wh1lo, 0, 0); CP_COMMIT();
    for (int ch = 0; ch < 8; ch++) {
        CP_WAIT0();
        __syncthreads();
        if (ch < 7) {
            issue_x(ch + 1, (ch + 1) & 1);
            issue_w(g_Wh1hi, g_Wh1lo, ch + 1, (ch + 1) & 1);
            CP_COMMIT();
        }
        computeN((const uint32_t*)sm + (ch & 1) * 2048, 32, 0,
                 (const uint32_t*)(sm + 32768 + (ch & 1) * 32768),
                 (const uint32_t*)(sm + 32768 + (ch & 1) * 32768 + 16384));
    }
    __syncthreads();   // last compute done before Ys (overlaps X bufs) is written

    // ---- epilogue 1: relu(x + b1) -> Ys (swizzled), zero c ----
#pragma unroll
    for (int nf = 0; nf < 8; nf++) {
        int cc = n0 + 8 * nf + 2 * t4;
        float bb0 = sb1[cc], bb1 = sb1[cc + 1];
        int w = (cc & ~31) + ((cc & 31) ^ (4 * g));
        *(float2*)&Ys[(m0 + g) * 128 + w] =
            make_float2(fmaxf(c[nf][0] + bb0, 0.0f), fmaxf(c[nf][1] + bb1, 0.0f));
        *(float2*)&Ys[(m0 + 8 + g) * 128 + w] =
            make_float2(fmaxf(c[nf][2] + bb0, 0.0f), fmaxf(c[nf][3] + bb1, 0.0f));
#pragma unroll
        for (int j = 0; j < 4; j++) c[nf][j] = 0.0f;
    }
    issue_w(g_Wh2hi, g_Wh2lo, 0, 0); CP_COMMIT();

    // ======== layer 2: K=128, 4 chunks — one sync per chunk ========
    for (int ch = 0; ch < 4; ch++) {
        CP_WAIT0();
        __syncthreads();   // ch0's sync also publishes epilogue Ys writes
        if (ch < 3) {
            issue_w(g_Wh2hi, g_Wh2lo, ch + 1, (ch + 1) & 1);
            CP_COMMIT();
        }
        computeN((const uint32_t*)sm, 128, ch * 32,
                 (const uint32_t*)(sm + 32768 + (ch & 1) * 32768),
                 (const uint32_t*)(sm + 32768 + (ch & 1) * 32768 + 16384));
    }

    // ---- store out = c + b2 (own accumulators only) ----
#pragma unroll
    for (int nf = 0; nf < 8; nf++) {
        int cc = n0 + 8 * nf + 2 * t4;
        float bb0 = sb2[cc], bb1 = sb2[cc + 1];
        int ra = r0 + m0 + g, rb = ra + 8;
        if (ra < N_NODES)
            *(float2*)(out + (size_t)ra * 128 + cc) =
                make_float2(c[nf][0] + bb0, c[nf][1] + bb1);
        if (rb < N_NODES)
            *(float2*)(out + (size_t)rb * 128 + cc) =
                make_float2(c[nf][2] + bb0, c[nf][3] + bb1);
    }
}

// =================================================================
extern "C" void kernel_launch(void* const* d_in, const int* in_sizes, int n_in,
                              void* d_out, int out_size) {
    const float* h   = (const float*)d_in[0];
    const void*  ei  = d_in[1];
    const float* ea  = (const float*)d_in[2];
    const float* We1 = (const float*)d_in[3];
    const float* be1 = (const float*)d_in[4];
    const float* We2 = (const float*)d_in[5];
    const float* be2 = (const float*)d_in[6];
    const float* Wh1 = (const float*)d_in[7];
    const float* bh1 = (const float*)d_in[8];
    const float* Wh2 = (const float*)d_in[9];
    const float* bh2 = (const float*)d_in[10];
    float* out = (float*)d_out;

    cudaFuncSetAttribute(edge_kernel_m, cudaFuncAttributeMaxDynamicSharedMemorySize, EDGE_SMEM);
    cudaFuncSetAttribute(gemm_P, cudaFuncAttributeMaxDynamicSharedMemorySize, GP_SMEM);
    cudaFuncSetAttribute(node_kernel_m, cudaFuncAttributeMaxDynamicSharedMemorySize, NODE_SMEM);

    convert_kernel<<<(N_EDGES + 255) / 256, 256>>>(ei);
    prep_kernel<<<64, 256>>>(We1, We2, Wh1, Wh2);
    gemm_P<<<(N_NODES + 127) / 128, 256, GP_SMEM>>>(h);
    edge_kernel_m<<<N_EDGES / 128, 256, EDGE_SMEM>>>(ea, be1, be2);
    node_kernel_m<<<(N_NODES + 63) / 64, 256, NODE_SMEM>>>(h, bh1, bh2, out);
}